// round 10
// baseline (speedup 1.0000x reference)
#include <cuda_runtime.h>
#include <math.h>

// Fixed shapes for BlurredMem_61950608278069
#define BS 128
#define W  256
#define N  2048
#define R  4
#define EPSF 1e-8f
#define CHW 4                 // k2x n-chunks (512 n per block, 2 per thread)

// Output layout: m_read (BS,R,W) | M_new (BS,W,N) | read_wt (BS,R,N)
#define OFF_MNEW (BS*R*W)
#define OFF_RWT  (BS*R*W + BS*W*N)

// moment planes (per (b,n)) produced by k2x
#define PL_EW 0               // exp(-cos) write weight numerator
#define PL_SA 1               // S0 = sum v^2
#define PL_SB 2               // T0 - S1
#define PL_SC 3               // S2 - 2*T1 + Swm
#define PL_A  4               // 4..7   A_r = sum kn_r * v
#define PL_D  8               // 8..11  D_r = C_r - B_r
#define NPL   12

typedef unsigned long long u64;

// -------- packed f32x2 helpers (Blackwell; ptxas never auto-fuses these) ---
__device__ __forceinline__ u64 pk2(float v) {
    u64 r; asm("mov.b64 %0, {%1,%1};" : "=l"(r) : "f"(v)); return r;
}
__device__ __forceinline__ u64 fma2(u64 a, u64 b, u64 c) {
    u64 d; asm("fma.rn.f32x2 %0, %1, %2, %3;" : "=l"(d) : "l"(a), "l"(b), "l"(c));
    return d;
}
__device__ __forceinline__ u64 mul2(u64 a, u64 b) {
    u64 d; asm("mul.rn.f32x2 %0, %1, %2;" : "=l"(d) : "l"(a), "l"(b));
    return d;
}
__device__ __forceinline__ float2 up2(u64 p) {
    float2 f; asm("mov.b64 {%0, %1}, %2;" : "=f"(f.x), "=f"(f.y) : "l"(p));
    return f;
}
__device__ __forceinline__ float hadd2(u64 p) { float2 f = up2(p); return f.x + f.y; }

union V2 { ulonglong2 u; float4 f; };

// -------- scratch (device globals) --------
__device__ float  g_wk[BS*W];        // unnormalized write key (relu'd)
__device__ float2 g_wmer[BS*W];      // (write_m, erase_vec)
__device__ float4 g_kn4[BS*W];       // normalized read keys (r packed)
__device__ float  g_mom[NPL*BS*N];   // per-column moments (12.6MB)
__device__ float  g_scal[BS*8];      // {Swm, C0..C3}
__device__ float  g_Zw_part[BS*CHW]; // per-block partial Zw

#define MOM(j) (g_mom + (size_t)(j)*BS*N)

// -------- block reduction: warp shuffles + one smem pass (256 threads) ----
template<int NV>
__device__ __forceinline__ void blk_reduce_sum(float (&v)[NV], float* sbuf) {
    const int lane = threadIdx.x & 31, wid = threadIdx.x >> 5;
    #pragma unroll
    for (int i = 0; i < NV; i++) {
        float x = v[i];
        #pragma unroll
        for (int o = 16; o; o >>= 1) x += __shfl_xor_sync(0xffffffffu, x, o);
        if (lane == 0) sbuf[i*8 + wid] = x;
    }
    __syncthreads();
    #pragma unroll
    for (int i = 0; i < NV; i++) {
        float s = 0.f;
        #pragma unroll
        for (int j = 0; j < 8; j++) s += sbuf[i*8 + j];
        v[i] = s;
    }
    __syncthreads();
}

// ===================== K1: per-batch prep (grid 4 x BS) =====================
__global__ void k1_prep(const float* __restrict__ k_r, const float* __restrict__ m_t,
                        const float* __restrict__ e_t, const float* __restrict__ m_er,
                        const float* __restrict__ gW,  const float* __restrict__ gb,
                        const float* __restrict__ oW,  const float* __restrict__ ob) {
    __shared__ float sbuf[64];
    __shared__ __align__(16) float s_cat[2*W];
    const int b = blockIdx.y, t = threadIdx.x;

    const float wm = tanhf(m_t[b*W + t]);
    const float me = m_er[b*W + t];
    const float ex = expf(e_t[b*W + t]);            // erase softmax, no max pass

    float kv[R];
    #pragma unroll
    for (int r = 0; r < R; r++) kv[r] = tanhf(k_r[(b*R + r)*W + t]);

    float v[6];
    v[0] = ex;
    v[1] = wm * gW[t] + me * gW[W + t];
    #pragma unroll
    for (int r = 0; r < R; r++) v[2+r] = kv[r] * kv[r];
    blk_reduce_sum<6>(v, sbuf);

    const float g  = 1.f / (1.f + expf(-(v[1] + gb[0])));
    const float er = ex / v[0];
    s_cat[t]     = g * wm;
    s_cat[W + t] = (1.f - g) * me;

    #pragma unroll
    for (int r = 0; r < R; r++) kv[r] /= (sqrtf(v[2+r]) + EPSF);

    // scalars: Swm = sum wm^2, C_r = sum kn_r * wm
    float s5[5] = { wm*wm, kv[0]*wm, kv[1]*wm, kv[2]*wm, kv[3]*wm };
    blk_reduce_sum<5>(s5, sbuf);

    if (blockIdx.x == 0) {
        g_wmer[b*W + t] = make_float2(wm, er);
        g_kn4[b*W + t]  = make_float4(kv[0], kv[1], kv[2], kv[3]);
        if (t < 5) g_scal[b*8 + t] = s5[t];
    }
    __syncthreads();

    // MLP: 64 rows per block, 4 threads per row
    const int o = blockIdx.x * 64 + (t >> 2);
    const int p = t & 3;
    const float4* orow4 = (const float4*)(oW + (size_t)o * 2 * W);
    const float4* sc4   = (const float4*)s_cat;
    float acc = 0.f;
    #pragma unroll 8
    for (int i = 0; i < 32; i++) {
        const int j = 4*i + p;
        float4 ow = orow4[j], sc = sc4[j];
        acc += ow.x*sc.x + ow.y*sc.y + ow.z*sc.z + ow.w*sc.w;
    }
    acc += __shfl_xor_sync(0xffffffffu, acc, 1);
    acc += __shfl_xor_sync(0xffffffffu, acc, 2);
    if (p == 0) g_wk[b*W + o] = fmaxf(acc + ob[o], 0.f);
}

// ===================== K2x: one pass over mem -> column moments (f32x2) ===
// Thread owns 2 adjacent columns; 15 packed ops per column-pair per w.
// Epilogue folds scalars: stores {EW, SA, SB, SC, A0..3, D0..3}.
__global__ void __launch_bounds__(256)
k2x_moments(const float* __restrict__ mem) {
    __shared__ __align__(16) ulonglong2 s_knA[W];   // {dup(kn0), dup(kn1)}
    __shared__ __align__(16) ulonglong2 s_knB[W];   // {dup(kn2), dup(kn3)}
    __shared__ __align__(16) ulonglong2 s_ewm[W];   // {dup(er),  dup(wm)}
    __shared__ u64  s_wkn[W];                       // dup(wkn)
    __shared__ float sbuf[8];
    const int b = blockIdx.y, t = threadIdx.x;

    // prologue: t == w  (write-key normalization)
    const float wk = g_wk[b*W + t];
    float v1[1] = { wk * wk };
    blk_reduce_sum<1>(v1, sbuf);
    const float wkn = wk / (sqrtf(v1[0]) + EPSF);
    const float2 me = g_wmer[b*W + t];              // (wm, er)
    const float4 kn = g_kn4[b*W + t];
    s_knA[t] = make_ulonglong2(pk2(kn.x), pk2(kn.y));
    s_knB[t] = make_ulonglong2(pk2(kn.z), pk2(kn.w));
    s_ewm[t] = make_ulonglong2(pk2(me.y), pk2(me.x));
    s_wkn[t] = pk2(wkn);
    __syncthreads();

    const int n0 = blockIdx.x * 512 + 2 * t;
    const u64* mp = (const u64*)(mem + (size_t)b * W * N + n0);

    u64 S0 = 0, S1 = 0, S2 = 0, T0 = 0, T1 = 0, dW = 0;
    u64 A0 = 0, A1 = 0, A2 = 0, A3 = 0;
    u64 B0 = 0, B1 = 0, B2 = 0, B3 = 0;
    #pragma unroll 16
    for (int w = 0; w < W; w++) {
        const u64 v = mp[(size_t)w * (N/2)];
        const ulonglong2 ka = s_knA[w];
        const ulonglong2 kb = s_knB[w];
        const ulonglong2 ew = s_ewm[w];             // {er2, wm2}
        const u64 u = mul2(ew.x, v);                // er * v
        S0 = fma2(v, v, S0);
        S1 = fma2(u, v, S1);
        S2 = fma2(u, u, S2);
        dW = fma2(s_wkn[w], v, dW);
        T0 = fma2(ew.y, v, T0);
        T1 = fma2(ew.y, u, T1);
        A0 = fma2(ka.x, v, A0);  A1 = fma2(ka.y, v, A1);
        A2 = fma2(kb.x, v, A2);  A3 = fma2(kb.y, v, A3);
        B0 = fma2(ka.x, u, B0);  B1 = fma2(ka.y, u, B1);
        B2 = fma2(kb.x, u, B2);  B3 = fma2(kb.y, u, B3);
    }

    const float Swm = g_scal[b*8 + 0];
    const float C0 = g_scal[b*8+1], C1 = g_scal[b*8+2];
    const float C2 = g_scal[b*8+3], C3 = g_scal[b*8+4];

    const float2 s0 = up2(S0), dw = up2(dW);
    const float2 s1 = up2(S1), s2 = up2(S2);
    const float2 t0 = up2(T0), t1 = up2(T1);
    float2 ew2;
    ew2.x = expf(-dw.x / (sqrtf(s0.x) + EPSF));
    ew2.y = expf(-dw.y / (sqrtf(s0.y) + EPSF));

    const size_t o = (size_t)b * N + n0;
    *(float2*)&MOM(PL_EW)[o] = ew2;
    *(float2*)&MOM(PL_SA)[o] = s0;
    *(float2*)&MOM(PL_SB)[o] = make_float2(t0.x - s1.x, t0.y - s1.y);
    *(float2*)&MOM(PL_SC)[o] = make_float2(s2.x - 2.f*t1.x + Swm,
                                           s2.y - 2.f*t1.y + Swm);
    float2 b0 = up2(B0), b1 = up2(B1), b2 = up2(B2), b3 = up2(B3);
    *(float2*)&MOM(PL_A+0)[o] = up2(A0);
    *(float2*)&MOM(PL_A+1)[o] = up2(A1);
    *(float2*)&MOM(PL_A+2)[o] = up2(A2);
    *(float2*)&MOM(PL_A+3)[o] = up2(A3);
    *(float2*)&MOM(PL_D+0)[o] = make_float2(C0 - b0.x, C0 - b0.y);
    *(float2*)&MOM(PL_D+1)[o] = make_float2(C1 - b1.x, C1 - b1.y);
    *(float2*)&MOM(PL_D+2)[o] = make_float2(C2 - b2.x, C2 - b2.y);
    *(float2*)&MOM(PL_D+3)[o] = make_float2(C3 - b3.x, C3 - b3.y);

    float z[1] = { ew2.x + ew2.y };
    blk_reduce_sum<1>(z, sbuf);
    if (t == 0) g_Zw_part[b*CHW + blockIdx.x] = z[0];
}

// ===================== K4y: staging (wwt,e,Zr,rwt) + M_new/m_read stream ==
// grid (8, BS). Staging: compute wwt + e_r from moments for the FULL batch
// (moments L2-resident across the 8 sibling blocks), block-reduce Zr, write
// this block's normalized rwt slice. Stream: warp owns 4 w-rows, computes
// M_new and accumulates P[row][r] += e_r * mn in packed registers.
__global__ void __launch_bounds__(256, 2)
k4y_stream(const float* __restrict__ mem, float* __restrict__ Mnew,
           float* __restrict__ rwt, float* __restrict__ mread) {
    __shared__ __align__(16) float s_wwt[N];      // 8 KB
    __shared__ __align__(16) float s_e[R][N];     // 32 KB
    __shared__ float sbuf[32];
    const int b = blockIdx.y, c = blockIdx.x;
    const int t = threadIdx.x, lane = t & 31, wi = t >> 5;

    float Zw = 0.f;
    #pragma unroll
    for (int k = 0; k < CHW; k++) Zw += g_Zw_part[b*CHW + k];
    const float iZw = 1.f / Zw;

    // ---- staging: full batch wwt + e_r, local Zr accumulation ----
    float zr[R] = {0.f, 0.f, 0.f, 0.f};
    #pragma unroll
    for (int k = 0; k < 8; k++) {
        const int n = t + k * 256;
        const size_t o = (size_t)b * N + n;
        const float wwt = MOM(PL_EW)[o] * iZw;
        s_wwt[n] = wwt;
        const float Sa = MOM(PL_SA)[o];
        const float Sb = MOM(PL_SB)[o];
        const float Sc = MOM(PL_SC)[o];
        const float nm2 = fmaf(wwt, fmaf(wwt, Sc, 2.f * Sb), Sa);
        const float inv = 1.f / (sqrtf(fmaxf(nm2, 0.f)) + EPSF);
        #pragma unroll
        for (int r = 0; r < R; r++) {
            const float Ar = MOM(PL_A+r)[o];
            const float Dr = MOM(PL_D+r)[o];
            const float e  = expf((fmaf(wwt, Dr, Ar)) * inv);
            s_e[r][n] = e;
            zr[r] += e;
        }
    }
    blk_reduce_sum<R>(zr, sbuf);   // includes __syncthreads (s_e now visible)

    // write this block's normalized rwt slice (256 float4 of 2048 per batch)
    {
        const int idx = c * 256 + t;            // float4 index in [0,2048)
        const int r = idx >> 9;
        const float s = 1.f / zr[r];
        float4 v = ((const float4*)s_e)[idx];
        v.x *= s; v.y *= s; v.z *= s; v.w *= s;
        ((float4*)(rwt + (size_t)b * R * N))[idx] = v;
    }

    // ---- stream phase ----
    const int w0 = c * 32 + wi * 4;
    u64 wm2[4], ner2[4];
    #pragma unroll
    for (int row = 0; row < 4; row++) {
        float2 me = g_wmer[b*W + w0 + row];
        wm2[row]  = pk2(me.x);
        ner2[row] = pk2(-me.y);
    }

    const ulonglong2* mp = (const ulonglong2*)(mem  + ((size_t)b*W + w0) * N);
    ulonglong2*       op = (ulonglong2*)(Mnew + ((size_t)b*W + w0) * N);
    const ulonglong2* sw = (const ulonglong2*)s_wwt;
    const ulonglong2* se0 = (const ulonglong2*)&s_e[0][0];
    const ulonglong2* se1 = (const ulonglong2*)&s_e[1][0];
    const ulonglong2* se2 = (const ulonglong2*)&s_e[2][0];
    const ulonglong2* se3 = (const ulonglong2*)&s_e[3][0];

    u64 P[4][R] = {};
    ulonglong2 vc[4];
    #pragma unroll
    for (int row = 0; row < 4; row++) vc[row] = mp[lane + row * (N/4)];

    #pragma unroll 2
    for (int k = 0; k < 16; k++) {
        const int idx  = lane + k * 32;
        const int nidx = (k < 15) ? idx + 32 : idx;
        ulonglong2 vn[4];
        #pragma unroll
        for (int row = 0; row < 4; row++) vn[row] = mp[nidx + row * (N/4)];

        const ulonglong2 ww = sw[idx];
        const ulonglong2 e0 = se0[idx], e1 = se1[idx];
        const ulonglong2 e2 = se2[idx], e3 = se3[idx];
        #pragma unroll
        for (int row = 0; row < 4; row++) {
            const ulonglong2 v = vc[row];
            // mn = wm*ww + (-er)*(v*ww) + v
            const u64 mna = fma2(wm2[row], ww.x, fma2(ner2[row], mul2(v.x, ww.x), v.x));
            const u64 mnb = fma2(wm2[row], ww.y, fma2(ner2[row], mul2(v.y, ww.y), v.y));
            V2 st; st.u = make_ulonglong2(mna, mnb);
            __stcs((float4*)&op[idx + row * (N/4)], st.f);
            P[row][0] = fma2(e0.x, mna, P[row][0]);
            P[row][0] = fma2(e0.y, mnb, P[row][0]);
            P[row][1] = fma2(e1.x, mna, P[row][1]);
            P[row][1] = fma2(e1.y, mnb, P[row][1]);
            P[row][2] = fma2(e2.x, mna, P[row][2]);
            P[row][2] = fma2(e2.y, mnb, P[row][2]);
            P[row][3] = fma2(e3.x, mna, P[row][3]);
            P[row][3] = fma2(e3.y, mnb, P[row][3]);
        }
        #pragma unroll
        for (int row = 0; row < 4; row++) vc[row] = vn[row];
    }

    // reduce packed accumulators and write m_read
    #pragma unroll
    for (int row = 0; row < 4; row++) {
        #pragma unroll
        for (int r = 0; r < R; r++) {
            float s = hadd2(P[row][r]);
            #pragma unroll
            for (int o2 = 16; o2; o2 >>= 1)
                s += __shfl_xor_sync(0xffffffffu, s, o2);
            if (lane == 0)
                mread[(size_t)b*R*W + r*W + w0 + row] = s / zr[r];
        }
    }
}

// ===================== launch =====================
extern "C" void kernel_launch(void* const* d_in, const int* in_sizes, int n_in,
                              void* d_out, int out_size) {
    const float* k_r   = (const float*)d_in[0];
    const float* m_t   = (const float*)d_in[1];
    const float* e_t   = (const float*)d_in[2];
    const float* m_er  = (const float*)d_in[3];
    const float* mem   = (const float*)d_in[4];
    const float* gW    = (const float*)d_in[5];
    const float* gb    = (const float*)d_in[6];
    const float* oW    = (const float*)d_in[7];
    const float* ob    = (const float*)d_in[8];

    float* out   = (float*)d_out;
    float* mread = out;               // (BS,R,W)
    float* Mnew  = out + OFF_MNEW;    // (BS,W,N)
    float* rwt   = out + OFF_RWT;     // (BS,R,N)

    k1_prep    <<<dim3(4,   BS), 256>>>(k_r, m_t, e_t, m_er, gW, gb, oW, ob);
    k2x_moments<<<dim3(CHW, BS), 256>>>(mem);
    k4y_stream <<<dim3(8,   BS), 256>>>(mem, Mnew, rwt, mread);
}

// round 11
// speedup vs baseline: 1.0913x; 1.0913x over previous
#include <cuda_runtime.h>
#include <math.h>

// Fixed shapes for BlurredMem_61950608278069
#define BS 128
#define W  256
#define N  2048
#define R  4
#define EPSF 1e-8f
#define CHW 4                 // k2x n-chunks (512 n per block, 2 per thread)

// Output layout: m_read (BS,R,W) | M_new (BS,W,N) | read_wt (BS,R,N)
#define OFF_MNEW (BS*R*W)
#define OFF_RWT  (BS*R*W + BS*W*N)

// moment planes (per (b,n)) produced by k2x  (scalars pre-folded)
#define PL_EW 0               // exp(-cos) write weight numerator
#define PL_SA 1               // S0 = sum v^2
#define PL_SB 2               // T0 - S1
#define PL_SC 3               // S2 - 2*T1 + Swm
#define PL_A  4               // 4..7   A_r = sum kn_r * v
#define PL_D  8               // 8..11  D_r = C_r - B_r
#define NPL   12

typedef unsigned long long u64;

// -------- packed f32x2 helpers (Blackwell; ptxas never auto-fuses these) ---
__device__ __forceinline__ u64 pk2(float v) {
    u64 r; asm("mov.b64 %0, {%1,%1};" : "=l"(r) : "f"(v)); return r;
}
__device__ __forceinline__ u64 fma2(u64 a, u64 b, u64 c) {
    u64 d; asm("fma.rn.f32x2 %0, %1, %2, %3;" : "=l"(d) : "l"(a), "l"(b), "l"(c));
    return d;
}
__device__ __forceinline__ u64 mul2(u64 a, u64 b) {
    u64 d; asm("mul.rn.f32x2 %0, %1, %2;" : "=l"(d) : "l"(a), "l"(b));
    return d;
}
__device__ __forceinline__ float2 up2(u64 p) {
    float2 f; asm("mov.b64 {%0, %1}, %2;" : "=f"(f.x), "=f"(f.y) : "l"(p));
    return f;
}
__device__ __forceinline__ float hadd2(u64 p) { float2 f = up2(p); return f.x + f.y; }

union V2 { ulonglong2 u; float4 f; };

// -------- scratch (device globals) --------
__device__ float  g_wk[BS*W];        // unnormalized write key (relu'd)
__device__ float2 g_wmer[BS*W];      // (write_m, erase_vec)
__device__ float4 g_kn4[BS*W];       // normalized read keys (r packed)
__device__ float  g_mom[NPL*BS*N];   // per-column moments (12.6MB)
__device__ float  g_scal[BS*8];      // {Swm, C0..C3}
__device__ float  g_Zw_part[BS*CHW]; // per-block partial Zw
__device__ float  g_wwt[BS*N];       // normalized write weights
__device__ float  g_rexp[BS*R*N];    // unnormalized read weights (scratch)
__device__ float4 g_Zr_part[BS*8];   // per-chunk Zr (4 heads)

#define MOM(j) (g_mom + (size_t)(j)*BS*N)

// -------- block reduction: warp shuffles + one smem pass (256 threads) ----
template<int NV>
__device__ __forceinline__ void blk_reduce_sum(float (&v)[NV], float* sbuf) {
    const int lane = threadIdx.x & 31, wid = threadIdx.x >> 5;
    #pragma unroll
    for (int i = 0; i < NV; i++) {
        float x = v[i];
        #pragma unroll
        for (int o = 16; o; o >>= 1) x += __shfl_xor_sync(0xffffffffu, x, o);
        if (lane == 0) sbuf[i*8 + wid] = x;
    }
    __syncthreads();
    #pragma unroll
    for (int i = 0; i < NV; i++) {
        float s = 0.f;
        #pragma unroll
        for (int j = 0; j < 8; j++) s += sbuf[i*8 + j];
        v[i] = s;
    }
    __syncthreads();
}

// ===================== K1: per-batch prep (grid 4 x BS) =====================
__global__ void k1_prep(const float* __restrict__ k_r, const float* __restrict__ m_t,
                        const float* __restrict__ e_t, const float* __restrict__ m_er,
                        const float* __restrict__ gW,  const float* __restrict__ gb,
                        const float* __restrict__ oW,  const float* __restrict__ ob) {
    __shared__ float sbuf[64];
    __shared__ __align__(16) float s_cat[2*W];
    const int b = blockIdx.y, t = threadIdx.x;

    const float wm = tanhf(m_t[b*W + t]);
    const float me = m_er[b*W + t];
    const float ex = expf(e_t[b*W + t]);            // erase softmax, no max pass

    float kv[R];
    #pragma unroll
    for (int r = 0; r < R; r++) kv[r] = tanhf(k_r[(b*R + r)*W + t]);

    float v[6];
    v[0] = ex;
    v[1] = wm * gW[t] + me * gW[W + t];
    #pragma unroll
    for (int r = 0; r < R; r++) v[2+r] = kv[r] * kv[r];
    blk_reduce_sum<6>(v, sbuf);

    const float g  = 1.f / (1.f + expf(-(v[1] + gb[0])));
    const float er = ex / v[0];
    s_cat[t]     = g * wm;
    s_cat[W + t] = (1.f - g) * me;

    #pragma unroll
    for (int r = 0; r < R; r++) kv[r] /= (sqrtf(v[2+r]) + EPSF);

    // scalars: Swm = sum wm^2, C_r = sum kn_r * wm
    float s5[5] = { wm*wm, kv[0]*wm, kv[1]*wm, kv[2]*wm, kv[3]*wm };
    blk_reduce_sum<5>(s5, sbuf);

    if (blockIdx.x == 0) {
        g_wmer[b*W + t] = make_float2(wm, er);
        g_kn4[b*W + t]  = make_float4(kv[0], kv[1], kv[2], kv[3]);
        if (t < 5) g_scal[b*8 + t] = s5[t];
    }
    __syncthreads();

    // MLP: 64 rows per block, 4 threads per row
    const int o = blockIdx.x * 64 + (t >> 2);
    const int p = t & 3;
    const float4* orow4 = (const float4*)(oW + (size_t)o * 2 * W);
    const float4* sc4   = (const float4*)s_cat;
    float acc = 0.f;
    #pragma unroll 8
    for (int i = 0; i < 32; i++) {
        const int j = 4*i + p;
        float4 ow = orow4[j], sc = sc4[j];
        acc += ow.x*sc.x + ow.y*sc.y + ow.z*sc.z + ow.w*sc.w;
    }
    acc += __shfl_xor_sync(0xffffffffu, acc, 1);
    acc += __shfl_xor_sync(0xffffffffu, acc, 2);
    if (p == 0) g_wk[b*W + o] = fmaxf(acc + ob[o], 0.f);
}

// ===================== K2x: one pass over mem -> column moments (f32x2) ===
// Thread owns 2 adjacent columns; 15 packed ops per column-pair per w.
// Epilogue folds scalars: stores {EW, SA, SB, SC, A0..3, D0..3}.
__global__ void __launch_bounds__(256, 3)
k2x_moments(const float* __restrict__ mem) {
    __shared__ __align__(16) ulonglong2 s_knA[W];   // {dup(kn0), dup(kn1)}
    __shared__ __align__(16) ulonglong2 s_knB[W];   // {dup(kn2), dup(kn3)}
    __shared__ __align__(16) ulonglong2 s_ewm[W];   // {dup(er),  dup(wm)}
    __shared__ u64  s_wkn[W];                       // dup(wkn)
    __shared__ float sbuf[8];
    const int b = blockIdx.y, t = threadIdx.x;

    // prologue: t == w  (write-key normalization)
    const float wk = g_wk[b*W + t];
    float v1[1] = { wk * wk };
    blk_reduce_sum<1>(v1, sbuf);
    const float wkn = wk / (sqrtf(v1[0]) + EPSF);
    const float2 me = g_wmer[b*W + t];              // (wm, er)
    const float4 kn = g_kn4[b*W + t];
    s_knA[t] = make_ulonglong2(pk2(kn.x), pk2(kn.y));
    s_knB[t] = make_ulonglong2(pk2(kn.z), pk2(kn.w));
    s_ewm[t] = make_ulonglong2(pk2(me.y), pk2(me.x));
    s_wkn[t] = pk2(wkn);
    __syncthreads();

    const int n0 = blockIdx.x * 512 + 2 * t;
    const u64* mp = (const u64*)(mem + (size_t)b * W * N + n0);

    u64 S0 = 0, S1 = 0, S2 = 0, T0 = 0, T1 = 0, dW = 0;
    u64 A0 = 0, A1 = 0, A2 = 0, A3 = 0;
    u64 B0 = 0, B1 = 0, B2 = 0, B3 = 0;
    #pragma unroll 16
    for (int w = 0; w < W; w++) {
        const u64 v = mp[(size_t)w * (N/2)];
        const ulonglong2 ka = s_knA[w];
        const ulonglong2 kb = s_knB[w];
        const ulonglong2 ew = s_ewm[w];             // {er2, wm2}
        const u64 u = mul2(ew.x, v);                // er * v
        S0 = fma2(v, v, S0);
        S1 = fma2(u, v, S1);
        S2 = fma2(u, u, S2);
        dW = fma2(s_wkn[w], v, dW);
        T0 = fma2(ew.y, v, T0);
        T1 = fma2(ew.y, u, T1);
        A0 = fma2(ka.x, v, A0);  A1 = fma2(ka.y, v, A1);
        A2 = fma2(kb.x, v, A2);  A3 = fma2(kb.y, v, A3);
        B0 = fma2(ka.x, u, B0);  B1 = fma2(ka.y, u, B1);
        B2 = fma2(kb.x, u, B2);  B3 = fma2(kb.y, u, B3);
    }

    const float Swm = g_scal[b*8 + 0];
    const float C0 = g_scal[b*8+1], C1 = g_scal[b*8+2];
    const float C2 = g_scal[b*8+3], C3 = g_scal[b*8+4];

    const float2 s0 = up2(S0), dw = up2(dW);
    const float2 s1 = up2(S1), s2 = up2(S2);
    const float2 t0 = up2(T0), t1 = up2(T1);
    float2 ew2;
    ew2.x = expf(-dw.x / (sqrtf(s0.x) + EPSF));
    ew2.y = expf(-dw.y / (sqrtf(s0.y) + EPSF));

    const size_t o = (size_t)b * N + n0;
    *(float2*)&MOM(PL_EW)[o] = ew2;
    *(float2*)&MOM(PL_SA)[o] = s0;
    *(float2*)&MOM(PL_SB)[o] = make_float2(t0.x - s1.x, t0.y - s1.y);
    *(float2*)&MOM(PL_SC)[o] = make_float2(s2.x - 2.f*t1.x + Swm,
                                           s2.y - 2.f*t1.y + Swm);
    float2 b0 = up2(B0), b1 = up2(B1), b2 = up2(B2), b3 = up2(B3);
    *(float2*)&MOM(PL_A+0)[o] = up2(A0);
    *(float2*)&MOM(PL_A+1)[o] = up2(A1);
    *(float2*)&MOM(PL_A+2)[o] = up2(A2);
    *(float2*)&MOM(PL_A+3)[o] = up2(A3);
    *(float2*)&MOM(PL_D+0)[o] = make_float2(C0 - b0.x, C0 - b0.y);
    *(float2*)&MOM(PL_D+1)[o] = make_float2(C1 - b1.x, C1 - b1.y);
    *(float2*)&MOM(PL_D+2)[o] = make_float2(C2 - b2.x, C2 - b2.y);
    *(float2*)&MOM(PL_D+3)[o] = make_float2(C3 - b3.x, C3 - b3.y);

    float z[1] = { ew2.x + ew2.y };
    blk_reduce_sum<1>(z, sbuf);
    if (t == 0) g_Zw_part[b*CHW + blockIdx.x] = z[0];
}

// ===================== K3x: per-column read weights from folded moments ===
__global__ void k3x_logits() {
    __shared__ float sbuf[32];
    const int b = blockIdx.y, t = threadIdx.x;
    const int n = blockIdx.x * 256 + t;
    const size_t o = (size_t)b * N + n;

    float Zw = 0.f;
    #pragma unroll
    for (int k = 0; k < CHW; k++) Zw += g_Zw_part[b*CHW + k];

    const float wwt = MOM(PL_EW)[o] / Zw;
    g_wwt[o] = wwt;

    const float Sa = MOM(PL_SA)[o];
    const float Sb = MOM(PL_SB)[o];
    const float Sc = MOM(PL_SC)[o];
    const float nm2 = fmaf(wwt, fmaf(wwt, Sc, 2.f * Sb), Sa);
    const float inv = 1.f / (sqrtf(fmaxf(nm2, 0.f)) + EPSF);

    float e4[R];
    #pragma unroll
    for (int r = 0; r < R; r++) {
        const float Ar = MOM(PL_A+r)[o];
        const float Dr = MOM(PL_D+r)[o];
        e4[r] = expf(fmaf(wwt, Dr, Ar) * inv);
        g_rexp[((size_t)b*R + r)*N + n] = e4[r];
    }
    blk_reduce_sum<R>(e4, sbuf);
    if (t == 0)
        g_Zr_part[b*8 + blockIdx.x] = make_float4(e4[0], e4[1], e4[2], e4[3]);
}

// ===================== K4x: M_new stream + m_read + normalized rwt ========
// grid (8, BS); warp owns 4 w-rows. Stages wwt + e (full batch) in smem;
// writes its normalized rwt output slice (no extra kernel); streams mem,
// writes M_new, accumulates P[row][r] += e_r * mn in packed registers.
__global__ void __launch_bounds__(256, 2)
k4x_stream(const float* __restrict__ mem, float* __restrict__ Mnew,
           float* __restrict__ rwt, float* __restrict__ mread) {
    __shared__ __align__(16) float s_wwt[N];      // 8 KB
    __shared__ __align__(16) float s_e[R][N];     // 32 KB
    const int b = blockIdx.y, c = blockIdx.x;
    const int t = threadIdx.x, lane = t & 31, wi = t >> 5;

    float Zr[R] = {0,0,0,0};
    #pragma unroll
    for (int k = 0; k < 8; k++) {
        float4 z = g_Zr_part[b*8 + k];
        Zr[0] += z.x; Zr[1] += z.y; Zr[2] += z.z; Zr[3] += z.w;
    }

    #pragma unroll
    for (int k = 0; k < 2; k++) {
        const int idx = t + k * 256;
        ((float4*)s_wwt)[idx] = ((const float4*)(g_wwt + (size_t)b*N))[idx];
        #pragma unroll
        for (int r = 0; r < R; r++)
            ((float4*)&s_e[r][0])[idx] =
                ((const float4*)(g_rexp + ((size_t)b*R + r)*N))[idx];
    }
    __syncthreads();

    // write this block's normalized rwt output slice (256 of 2048 float4)
    {
        const int idx = c * 256 + t;
        const int r = idx >> 9;
        const float s = 1.f / Zr[r];
        float4 v = ((const float4*)s_e)[idx];
        v.x *= s; v.y *= s; v.z *= s; v.w *= s;
        ((float4*)(rwt + (size_t)b * R * N))[idx] = v;
    }

    const int w0 = c * 32 + wi * 4;
    u64 wm2[4], ner2[4];
    #pragma unroll
    for (int row = 0; row < 4; row++) {
        float2 me = g_wmer[b*W + w0 + row];
        wm2[row]  = pk2(me.x);
        ner2[row] = pk2(-me.y);
    }

    const ulonglong2* mp = (const ulonglong2*)(mem  + ((size_t)b*W + w0) * N);
    ulonglong2*       op = (ulonglong2*)(Mnew + ((size_t)b*W + w0) * N);
    const ulonglong2* sw = (const ulonglong2*)s_wwt;
    const ulonglong2* se0 = (const ulonglong2*)&s_e[0][0];
    const ulonglong2* se1 = (const ulonglong2*)&s_e[1][0];
    const ulonglong2* se2 = (const ulonglong2*)&s_e[2][0];
    const ulonglong2* se3 = (const ulonglong2*)&s_e[3][0];

    u64 P[4][R] = {};
    ulonglong2 vc[4];
    #pragma unroll
    for (int row = 0; row < 4; row++) vc[row] = mp[lane + row * (N/4)];

    #pragma unroll 2
    for (int k = 0; k < 16; k++) {
        const int idx  = lane + k * 32;
        const int nidx = (k < 15) ? idx + 32 : idx;
        ulonglong2 vn[4];
        #pragma unroll
        for (int row = 0; row < 4; row++) vn[row] = mp[nidx + row * (N/4)];

        const ulonglong2 ww = sw[idx];
        const ulonglong2 e0 = se0[idx], e1 = se1[idx];
        const ulonglong2 e2 = se2[idx], e3 = se3[idx];
        #pragma unroll
        for (int row = 0; row < 4; row++) {
            const ulonglong2 v = vc[row];
            // mn = wm*ww + (-er)*(v*ww) + v
            const u64 mna = fma2(wm2[row], ww.x, fma2(ner2[row], mul2(v.x, ww.x), v.x));
            const u64 mnb = fma2(wm2[row], ww.y, fma2(ner2[row], mul2(v.y, ww.y), v.y));
            V2 st; st.u = make_ulonglong2(mna, mnb);
            __stcs((float4*)&op[idx + row * (N/4)], st.f);
            P[row][0] = fma2(e0.x, mna, P[row][0]);
            P[row][0] = fma2(e0.y, mnb, P[row][0]);
            P[row][1] = fma2(e1.x, mna, P[row][1]);
            P[row][1] = fma2(e1.y, mnb, P[row][1]);
            P[row][2] = fma2(e2.x, mna, P[row][2]);
            P[row][2] = fma2(e2.y, mnb, P[row][2]);
            P[row][3] = fma2(e3.x, mna, P[row][3]);
            P[row][3] = fma2(e3.y, mnb, P[row][3]);
        }
        #pragma unroll
        for (int row = 0; row < 4; row++) vc[row] = vn[row];
    }

    // reduce packed accumulators and write m_read
    #pragma unroll
    for (int row = 0; row < 4; row++) {
        #pragma unroll
        for (int r = 0; r < R; r++) {
            float s = hadd2(P[row][r]);
            #pragma unroll
            for (int o2 = 16; o2; o2 >>= 1)
                s += __shfl_xor_sync(0xffffffffu, s, o2);
            if (lane == 0)
                mread[(size_t)b*R*W + r*W + w0 + row] = s / Zr[r];
        }
    }
}

// ===================== launch =====================
extern "C" void kernel_launch(void* const* d_in, const int* in_sizes, int n_in,
                              void* d_out, int out_size) {
    const float* k_r   = (const float*)d_in[0];
    const float* m_t   = (const float*)d_in[1];
    const float* e_t   = (const float*)d_in[2];
    const float* m_er  = (const float*)d_in[3];
    const float* mem   = (const float*)d_in[4];
    const float* gW    = (const float*)d_in[5];
    const float* gb    = (const float*)d_in[6];
    const float* oW    = (const float*)d_in[7];
    const float* ob    = (const float*)d_in[8];

    float* out   = (float*)d_out;
    float* mread = out;               // (BS,R,W)
    float* Mnew  = out + OFF_MNEW;    // (BS,W,N)
    float* rwt   = out + OFF_RWT;     // (BS,R,N)

    k1_prep    <<<dim3(4,   BS), 256>>>(k_r, m_t, e_t, m_er, gW, gb, oW, ob);
    k2x_moments<<<dim3(CHW, BS), 256>>>(mem);
    k3x_logits <<<dim3(8,   BS), 256>>>();
    k4x_stream <<<dim3(8,   BS), 256>>>(mem, Mnew, rwt, mread);
}